// round 1
// baseline (speedup 1.0000x reference)
#include <cuda_runtime.h>
#include <cuda_bf16.h>

// CenterLoss: out = LAMBDA_C * mean_b ||features[b] - centers[labels[b]]||^2
// B = 65536, D = 256, C = 100000. LAMBDA_C = 1.0.
//
// Strategy: 1 warp per batch row. Each lane loads 2x float4 from the feature
// row and 2x float4 from the gathered center row (32 lanes * 8 floats = 256).
// Warp shuffle reduction -> per-block partial (8 rows/block). A second tiny
// kernel reduces the 8192 partials in double precision and scales by 1/B.
// No atomics, no scratch zeroing needed (partials fully rewritten per replay).

#define D 256
#define WARPS_PER_BLOCK 8
#define MAX_PARTIALS 16384

__device__ float g_partials[MAX_PARTIALS];

__global__ void center_loss_main(const float* __restrict__ feat,
                                 const int* __restrict__ labels,
                                 const float* __restrict__ centers,
                                 int B) {
    const int warp = threadIdx.x >> 5;
    const int lane = threadIdx.x & 31;
    const int row  = blockIdx.x * WARPS_PER_BLOCK + warp;

    float acc = 0.0f;
    if (row < B) {
        const float4* __restrict__ f =
            reinterpret_cast<const float4*>(feat + (size_t)row * D);
        const long long c = labels[row];
        const float4* __restrict__ cp =
            reinterpret_cast<const float4*>(centers + (size_t)c * D);

        // Two coalesced float4 loads per lane from each array.
        float4 a0 = f[lane];
        float4 b0 = cp[lane];
        float4 a1 = f[lane + 32];
        float4 b1 = cp[lane + 32];

        float d;
        d = a0.x - b0.x; acc = fmaf(d, d, acc);
        d = a0.y - b0.y; acc = fmaf(d, d, acc);
        d = a0.z - b0.z; acc = fmaf(d, d, acc);
        d = a0.w - b0.w; acc = fmaf(d, d, acc);
        d = a1.x - b1.x; acc = fmaf(d, d, acc);
        d = a1.y - b1.y; acc = fmaf(d, d, acc);
        d = a1.z - b1.z; acc = fmaf(d, d, acc);
        d = a1.w - b1.w; acc = fmaf(d, d, acc);
    }

    // Warp reduction
    #pragma unroll
    for (int o = 16; o > 0; o >>= 1)
        acc += __shfl_xor_sync(0xFFFFFFFFu, acc, o);

    __shared__ float s[WARPS_PER_BLOCK];
    if (lane == 0) s[warp] = acc;
    __syncthreads();

    if (threadIdx.x == 0) {
        float t = 0.0f;
        #pragma unroll
        for (int i = 0; i < WARPS_PER_BLOCK; i++) t += s[i];
        g_partials[blockIdx.x] = t;
    }
}

__global__ void center_loss_finalize(float* __restrict__ out, int nblocks, int B) {
    __shared__ double s[256];
    double t = 0.0;
    for (int i = threadIdx.x; i < nblocks; i += 256)
        t += (double)g_partials[i];
    s[threadIdx.x] = t;
    __syncthreads();
    #pragma unroll
    for (int stride = 128; stride > 0; stride >>= 1) {
        if (threadIdx.x < stride) s[threadIdx.x] += s[threadIdx.x + stride];
        __syncthreads();
    }
    if (threadIdx.x == 0)
        out[0] = (float)(s[0] / (double)B);   // LAMBDA_C = 1.0
}

extern "C" void kernel_launch(void* const* d_in, const int* in_sizes, int n_in,
                              void* d_out, int out_size) {
    const float* feat    = (const float*)d_in[0];
    const int*   labels  = (const int*)d_in[1];
    const float* centers = (const float*)d_in[2];
    float*       out     = (float*)d_out;

    const int B = in_sizes[1];                       // label count = batch
    const int nblocks = (B + WARPS_PER_BLOCK - 1) / WARPS_PER_BLOCK;

    center_loss_main<<<nblocks, WARPS_PER_BLOCK * 32>>>(feat, labels, centers, B);
    center_loss_finalize<<<1, 256>>>(out, nblocks, B);
}

// round 2
// speedup vs baseline: 1.1545x; 1.1545x over previous
#include <cuda_runtime.h>
#include <cuda_bf16.h>

// CenterLoss: out = mean_b ||features[b] - centers[labels[b]]||^2
// B = 65536, D = 256, C = 100000, LAMBDA_C = 1.0.
//
// Single kernel: warp-per-row gather + squared distance, 4 rows per warp
// (independent chains -> MLP), block partial -> last-block-done final
// reduction in double. Counter wraps at gridDim so it self-resets across
// CUDA-graph replays (no zeroing launch, no second kernel).

#define D 256
#define WARPS_PER_BLOCK 8
#define NBLOCKS 2048            // 2048 blocks * 8 warps * 4 rows = 65536

__device__ float g_partials[NBLOCKS];
__device__ unsigned int g_ctr = 0;

__global__ __launch_bounds__(WARPS_PER_BLOCK * 32)
void center_loss_fused(const float* __restrict__ feat,
                       const int* __restrict__ labels,
                       const float* __restrict__ centers,
                       float* __restrict__ out, int B) {
    const int warp = threadIdx.x >> 5;
    const int lane = threadIdx.x & 31;
    const int gw   = blockIdx.x * WARPS_PER_BLOCK + warp;
    const int W    = gridDim.x * WARPS_PER_BLOCK;

    float acc = 0.0f;
    #pragma unroll 4
    for (int row = gw; row < B; row += W) {
        const long long c = labels[row];
        const float4* __restrict__ f =
            reinterpret_cast<const float4*>(feat + (size_t)row * D);
        const float4* __restrict__ cp =
            reinterpret_cast<const float4*>(centers + (size_t)c * D);

        float4 a0 = f[lane];
        float4 b0 = cp[lane];
        float4 a1 = f[lane + 32];
        float4 b1 = cp[lane + 32];

        float d;
        d = a0.x - b0.x; acc = fmaf(d, d, acc);
        d = a0.y - b0.y; acc = fmaf(d, d, acc);
        d = a0.z - b0.z; acc = fmaf(d, d, acc);
        d = a0.w - b0.w; acc = fmaf(d, d, acc);
        d = a1.x - b1.x; acc = fmaf(d, d, acc);
        d = a1.y - b1.y; acc = fmaf(d, d, acc);
        d = a1.z - b1.z; acc = fmaf(d, d, acc);
        d = a1.w - b1.w; acc = fmaf(d, d, acc);
    }

    // Warp reduction (fixed tree -> deterministic)
    #pragma unroll
    for (int o = 16; o > 0; o >>= 1)
        acc += __shfl_xor_sync(0xFFFFFFFFu, acc, o);

    __shared__ float s[WARPS_PER_BLOCK];
    __shared__ bool is_last;
    if (lane == 0) s[warp] = acc;
    __syncthreads();

    if (threadIdx.x == 0) {
        float t = 0.0f;
        #pragma unroll
        for (int i = 0; i < WARPS_PER_BLOCK; i++) t += s[i];
        g_partials[blockIdx.x] = t;
        __threadfence();
        // atomicInc wraps to 0 after gridDim.x increments -> self-resets
        // for every graph replay.
        unsigned int old = atomicInc(&g_ctr, gridDim.x - 1);
        is_last = (old == gridDim.x - 1);
    }
    __syncthreads();

    if (!is_last) return;

    // Last block: deterministic reduction of NBLOCKS partials in double.
    __shared__ double sd[256];
    const volatile float* vp = g_partials;
    double t = 0.0;
    for (int i = threadIdx.x; i < NBLOCKS; i += 256)
        t += (double)vp[i];
    sd[threadIdx.x] = t;
    __syncthreads();
    #pragma unroll
    for (int stride = 128; stride > 0; stride >>= 1) {
        if (threadIdx.x < stride) sd[threadIdx.x] += sd[threadIdx.x + stride];
        __syncthreads();
    }
    if (threadIdx.x == 0)
        out[0] = (float)(sd[0] / (double)B);   // LAMBDA_C = 1.0
}

extern "C" void kernel_launch(void* const* d_in, const int* in_sizes, int n_in,
                              void* d_out, int out_size) {
    const float* feat    = (const float*)d_in[0];
    const int*   labels  = (const int*)d_in[1];
    const float* centers = (const float*)d_in[2];
    float*       out     = (float*)d_out;

    const int B = in_sizes[1];   // 65536

    center_loss_fused<<<NBLOCKS, WARPS_PER_BLOCK * 32>>>(feat, labels, centers, out, B);
}

// round 3
// speedup vs baseline: 1.2237x; 1.0599x over previous
#include <cuda_runtime.h>
#include <cuda_bf16.h>

// CenterLoss: out = mean_b ||features[b] - centers[labels[b]]||^2
// B = 65536, D = 256, C = 100000, LAMBDA_C = 1.0.
//
// Warp owns 4 consecutive rows, no loop:
//   - one int4 broadcast load -> 4 labels (single label-load latency)
//   - 16 float4 loads issued back-to-back (MLP ~16/warp)
//   - features via __ldcs (streaming, evict-first) so centers keep L2
// Block partial -> last-block-done double reduction (self-resetting counter,
// graph-replay safe).

#define D 256
#define WARPS_PER_BLOCK 8
#define ROWS_PER_WARP 4
#define NBLOCKS 2048   // 2048 * 8 warps * 4 rows = 65536 = B

__device__ float g_partials[NBLOCKS];
__device__ unsigned int g_ctr = 0;

__global__ __launch_bounds__(WARPS_PER_BLOCK * 32)
void center_loss_fused(const float* __restrict__ feat,
                       const int* __restrict__ labels,
                       const float* __restrict__ centers,
                       float* __restrict__ out, int B) {
    const int warp = threadIdx.x >> 5;
    const int lane = threadIdx.x & 31;
    const int row0 = (blockIdx.x * WARPS_PER_BLOCK + warp) * ROWS_PER_WARP;

    // One broadcast int4 load: labels for all 4 rows of this warp.
    const int4 lab = *reinterpret_cast<const int4*>(labels + row0);

    const float4* f0 = reinterpret_cast<const float4*>(feat + (size_t)(row0 + 0) * D) + lane;
    const float4* f1 = reinterpret_cast<const float4*>(feat + (size_t)(row0 + 1) * D) + lane;
    const float4* f2 = reinterpret_cast<const float4*>(feat + (size_t)(row0 + 2) * D) + lane;
    const float4* f3 = reinterpret_cast<const float4*>(feat + (size_t)(row0 + 3) * D) + lane;
    const float4* c0 = reinterpret_cast<const float4*>(centers + (size_t)lab.x * D) + lane;
    const float4* c1 = reinterpret_cast<const float4*>(centers + (size_t)lab.y * D) + lane;
    const float4* c2 = reinterpret_cast<const float4*>(centers + (size_t)lab.z * D) + lane;
    const float4* c3 = reinterpret_cast<const float4*>(centers + (size_t)lab.w * D) + lane;

    // Issue all 16 loads back-to-back (streaming hint on features).
    float4 a00 = __ldcs(f0);      float4 a01 = __ldcs(f0 + 32);
    float4 a10 = __ldcs(f1);      float4 a11 = __ldcs(f1 + 32);
    float4 a20 = __ldcs(f2);      float4 a21 = __ldcs(f2 + 32);
    float4 a30 = __ldcs(f3);      float4 a31 = __ldcs(f3 + 32);
    float4 b00 = __ldg(c0);       float4 b01 = __ldg(c0 + 32);
    float4 b10 = __ldg(c1);       float4 b11 = __ldg(c1 + 32);
    float4 b20 = __ldg(c2);       float4 b21 = __ldg(c2 + 32);
    float4 b30 = __ldg(c3);       float4 b31 = __ldg(c3 + 32);

    float s0 = 0.f, s1 = 0.f, s2 = 0.f, s3 = 0.f;
    float d;
    d = a00.x - b00.x; s0 = fmaf(d, d, s0);
    d = a00.y - b00.y; s0 = fmaf(d, d, s0);
    d = a00.z - b00.z; s0 = fmaf(d, d, s0);
    d = a00.w - b00.w; s0 = fmaf(d, d, s0);
    d = a01.x - b01.x; s0 = fmaf(d, d, s0);
    d = a01.y - b01.y; s0 = fmaf(d, d, s0);
    d = a01.z - b01.z; s0 = fmaf(d, d, s0);
    d = a01.w - b01.w; s0 = fmaf(d, d, s0);

    d = a10.x - b10.x; s1 = fmaf(d, d, s1);
    d = a10.y - b10.y; s1 = fmaf(d, d, s1);
    d = a10.z - b10.z; s1 = fmaf(d, d, s1);
    d = a10.w - b10.w; s1 = fmaf(d, d, s1);
    d = a11.x - b11.x; s1 = fmaf(d, d, s1);
    d = a11.y - b11.y; s1 = fmaf(d, d, s1);
    d = a11.z - b11.z; s1 = fmaf(d, d, s1);
    d = a11.w - b11.w; s1 = fmaf(d, d, s1);

    d = a20.x - b20.x; s2 = fmaf(d, d, s2);
    d = a20.y - b20.y; s2 = fmaf(d, d, s2);
    d = a20.z - b20.z; s2 = fmaf(d, d, s2);
    d = a20.w - b20.w; s2 = fmaf(d, d, s2);
    d = a21.x - b21.x; s2 = fmaf(d, d, s2);
    d = a21.y - b21.y; s2 = fmaf(d, d, s2);
    d = a21.z - b21.z; s2 = fmaf(d, d, s2);
    d = a21.w - b21.w; s2 = fmaf(d, d, s2);

    d = a30.x - b30.x; s3 = fmaf(d, d, s3);
    d = a30.y - b30.y; s3 = fmaf(d, d, s3);
    d = a30.z - b30.z; s3 = fmaf(d, d, s3);
    d = a30.w - b30.w; s3 = fmaf(d, d, s3);
    d = a31.x - b31.x; s3 = fmaf(d, d, s3);
    d = a31.y - b31.y; s3 = fmaf(d, d, s3);
    d = a31.z - b31.z; s3 = fmaf(d, d, s3);
    d = a31.w - b31.w; s3 = fmaf(d, d, s3);

    float acc = (s0 + s1) + (s2 + s3);

    // Warp reduction (fixed tree -> deterministic)
    #pragma unroll
    for (int o = 16; o > 0; o >>= 1)
        acc += __shfl_xor_sync(0xFFFFFFFFu, acc, o);

    __shared__ float s[WARPS_PER_BLOCK];
    __shared__ bool is_last;
    if (lane == 0) s[warp] = acc;
    __syncthreads();

    if (threadIdx.x == 0) {
        float t = 0.0f;
        #pragma unroll
        for (int i = 0; i < WARPS_PER_BLOCK; i++) t += s[i];
        g_partials[blockIdx.x] = t;
        __threadfence();
        unsigned int old = atomicInc(&g_ctr, gridDim.x - 1);  // wraps -> replay-safe
        is_last = (old == gridDim.x - 1);
    }
    __syncthreads();

    if (!is_last) return;

    __shared__ double sd[256];
    const volatile float* vp = g_partials;
    double t = 0.0;
    for (int i = threadIdx.x; i < NBLOCKS; i += 256)
        t += (double)vp[i];
    sd[threadIdx.x] = t;
    __syncthreads();
    #pragma unroll
    for (int stride = 128; stride > 0; stride >>= 1) {
        if (threadIdx.x < stride) sd[threadIdx.x] += sd[threadIdx.x + stride];
        __syncthreads();
    }
    if (threadIdx.x == 0)
        out[0] = (float)(sd[0] / (double)B);   // LAMBDA_C = 1.0
}

extern "C" void kernel_launch(void* const* d_in, const int* in_sizes, int n_in,
                              void* d_out, int out_size) {
    const float* feat    = (const float*)d_in[0];
    const int*   labels  = (const int*)d_in[1];
    const float* centers = (const float*)d_in[2];
    float*       out     = (float*)d_out;

    const int B = in_sizes[1];   // 65536

    center_loss_fused<<<NBLOCKS, WARPS_PER_BLOCK * 32>>>(feat, labels, centers, out, B);
}

// round 5
// speedup vs baseline: 1.2764x; 1.0431x over previous
#include <cuda_runtime.h>
#include <cuda_bf16.h>

// CenterLoss: out = mean_b ||features[b] - centers[labels[b]]||^2
// B = 65536, D = 256, C = 100000, LAMBDA_C = 1.0.
//
// Warp owns 4 consecutive rows. 256-bit loads: one ld.global.nc.v4.b64 per
// lane covers 32B -> whole 1KB row per warp in ONE instruction. 8 asm
// volatile loads back-to-back (guaranteed front-batched, MLP=8x1KB/warp).
// L2 policy: centers evict_last (labels identical across graph replays ->
// touched ~48MB stays L2-resident), features evict_first (one-pass stream).
// Block partial -> last-block-done double reduction; wrapping atomic counter
// self-resets across replays.

#define D 256
#define WARPS_PER_BLOCK 8
#define ROWS_PER_WARP 4
#define NBLOCKS 2048   // 2048 * 8 * 4 = 65536 = B

__device__ float g_partials[NBLOCKS];
__device__ unsigned int g_ctr = 0;

struct V8 { unsigned long long u[4]; };

// Streamed 256-bit load (features: one-pass, evict first)
__device__ __forceinline__ V8 ld_stream(const void* p) {
    V8 v;
    asm volatile("ld.global.nc.L1::evict_first.L2::evict_first.v4.b64 {%0,%1,%2,%3}, [%4];"
                 : "=l"(v.u[0]), "=l"(v.u[1]), "=l"(v.u[2]), "=l"(v.u[3]) : "l"(p));
    return v;
}
// Sticky 256-bit load (centers: keep in L2 across replays)
__device__ __forceinline__ V8 ld_sticky(const void* p) {
    V8 v;
    asm volatile("ld.global.nc.L2::evict_last.v4.b64 {%0,%1,%2,%3}, [%4];"
                 : "=l"(v.u[0]), "=l"(v.u[1]), "=l"(v.u[2]), "=l"(v.u[3]) : "l"(p));
    return v;
}

// acc += sum((a-b)^2) over the 8 packed floats
__device__ __forceinline__ float sq8(const V8& a, const V8& b, float s) {
    #pragma unroll
    for (int i = 0; i < 4; i++) {
        float2 af = *reinterpret_cast<const float2*>(&a.u[i]);
        float2 bf = *reinterpret_cast<const float2*>(&b.u[i]);
        float d0 = af.x - bf.x; s = fmaf(d0, d0, s);
        float d1 = af.y - bf.y; s = fmaf(d1, d1, s);
    }
    return s;
}

__global__ __launch_bounds__(WARPS_PER_BLOCK * 32)
void center_loss_fused(const float* __restrict__ feat,
                       const int* __restrict__ labels,
                       const float* __restrict__ centers,
                       float* __restrict__ out, int B) {
    const int warp = threadIdx.x >> 5;
    const int lane = threadIdx.x & 31;
    const int row0 = (blockIdx.x * WARPS_PER_BLOCK + warp) * ROWS_PER_WARP;

    // One broadcast int4 load: labels for all 4 rows of this warp.
    const int4 lab = *reinterpret_cast<const int4*>(labels + row0);

    // Each lane owns elements [lane*8, lane*8+8) of each row (32B, aligned).
    const char* fbase = reinterpret_cast<const char*>(feat) + (size_t)row0 * D * 4 + lane * 32;
    const char* cbase = reinterpret_cast<const char*>(centers);

    const void* f0 = fbase;
    const void* f1 = fbase + 1 * D * 4;
    const void* f2 = fbase + 2 * D * 4;
    const void* f3 = fbase + 3 * D * 4;
    const void* c0 = cbase + (size_t)lab.x * D * 4 + lane * 32;
    const void* c1 = cbase + (size_t)lab.y * D * 4 + lane * 32;
    const void* c2 = cbase + (size_t)lab.z * D * 4 + lane * 32;
    const void* c3 = cbase + (size_t)lab.w * D * 4 + lane * 32;

    // 8 loads, front-batched (asm volatile keeps issue order).
    V8 b0 = ld_sticky(c0);
    V8 b1 = ld_sticky(c1);
    V8 b2 = ld_sticky(c2);
    V8 b3 = ld_sticky(c3);
    V8 a0 = ld_stream(f0);
    V8 a1 = ld_stream(f1);
    V8 a2 = ld_stream(f2);
    V8 a3 = ld_stream(f3);

    float s0 = sq8(a0, b0, 0.0f);
    float s1 = sq8(a1, b1, 0.0f);
    float s2 = sq8(a2, b2, 0.0f);
    float s3 = sq8(a3, b3, 0.0f);
    float acc = (s0 + s1) + (s2 + s3);

    // Warp reduction (fixed tree -> deterministic)
    #pragma unroll
    for (int o = 16; o > 0; o >>= 1)
        acc += __shfl_xor_sync(0xFFFFFFFFu, acc, o);

    __shared__ float s[WARPS_PER_BLOCK];
    __shared__ bool is_last;
    if (lane == 0) s[warp] = acc;
    __syncthreads();

    if (threadIdx.x == 0) {
        float t = 0.0f;
        #pragma unroll
        for (int i = 0; i < WARPS_PER_BLOCK; i++) t += s[i];
        g_partials[blockIdx.x] = t;
        __threadfence();
        unsigned int old = atomicInc(&g_ctr, gridDim.x - 1);  // wraps -> replay-safe
        is_last = (old == gridDim.x - 1);
    }
    __syncthreads();

    if (!is_last) return;

    __shared__ double sd[256];
    const volatile float* vp = g_partials;
    double t = 0.0;
    for (int i = threadIdx.x; i < NBLOCKS; i += 256)
        t += (double)vp[i];
    sd[threadIdx.x] = t;
    __syncthreads();
    #pragma unroll
    for (int stride = 128; stride > 0; stride >>= 1) {
        if (threadIdx.x < stride) sd[threadIdx.x] += sd[threadIdx.x + stride];
        __syncthreads();
    }
    if (threadIdx.x == 0)
        out[0] = (float)(sd[0] / (double)B);   // LAMBDA_C = 1.0
}

extern "C" void kernel_launch(void* const* d_in, const int* in_sizes, int n_in,
                              void* d_out, int out_size) {
    const float* feat    = (const float*)d_in[0];
    const int*   labels  = (const int*)d_in[1];
    const float* centers = (const float*)d_in[2];
    float*       out     = (float*)d_out;

    const int B = in_sizes[1];   // 65536

    center_loss_fused<<<NBLOCKS, WARPS_PER_BLOCK * 32>>>(feat, labels, centers, out, B);
}